// round 16
// baseline (speedup 1.0000x reference)
#include <cuda_runtime.h>
#include <cstdint>

// Problem constants
#define BMAX 16
#define PRE 2000
#define PREP 2048          // padded
#define NCH 32             // PREP/64
#define POST 1000
#define CAND_MAX 4096
#define NBINS 65536
#define IOU_T 0.7f
#define IMGSZ 800.0f
#define BBOX_CLIP 4.135166556742356f   // log(1000/16)
#define TRI_BLOCKS ((NCH * (NCH + 1)) / 2)   // 528 upper-triangle chunk pairs
#define JSPLIT 4
#define SLICE_MAX (CAND_MAX / JSPLIT)        // 1024

// ---------------- device scratch (no allocation allowed) ----------------
__device__ int                g_hist[BMAX * NBINS];      // 4 MB
__device__ unsigned int       g_bstar[BMAX];
__device__ int                g_ccount[BMAX];
__device__ unsigned long long g_cand[BMAX * CAND_MAX];   // 0.5 MB
__device__ int                g_rank[BMAX * CAND_MAX];   // 0.25 MB
__device__ float              g_boxes[BMAX * PREP * 4];  // 0.5 MB (rows >= PRE stay zero)
__device__ float              g_logit[BMAX * PREP];
__device__ unsigned long long g_mask[BMAX * PREP * NCH]; // 8 MB (upper triangle valid)

__device__ __forceinline__ unsigned int flip_key(float f) {
    unsigned int u = __float_as_uint(f);
    return (u & 0x80000000u) ? ~u : (u | 0x80000000u);
}

// ---------------- kernels ----------------
// float2 vectorized: 2 elems per LDG.64
__global__ void k_hist(const float* __restrict__ scores, int A) {
    int img = blockIdx.y;
    int i = blockIdx.x * blockDim.x + threadIdx.x;
    int n2 = A >> 1;
    if (i >= n2) return;
    const float2* p = (const float2*)(scores + (size_t)img * A);
    float2 v = p[i];
    atomicAdd(&g_hist[img * NBINS + (flip_key(v.x) >> 16)], 1);
    atomicAdd(&g_hist[img * NBINS + (flip_key(v.y) >> 16)], 1);
}

// one block (1024 thr) per image: boundary bin b*
__global__ void k_select() {
    int img = blockIdx.x;
    int tid = threadIdx.x;           // 1024
    int lane = tid & 31, wid = tid >> 5;
    const int* h = &g_hist[img * NBINS];
    int lo = tid * 64;
    int cs = 0;
    const int4* h4 = (const int4*)(h + lo);
    #pragma unroll
    for (int v = 0; v < 16; v++) { int4 x = h4[v]; cs += x.x + x.y + x.z + x.w; }
    int suf = cs;
    #pragma unroll
    for (int off = 1; off < 32; off <<= 1) {
        int v = __shfl_down_sync(0xffffffffu, suf, off);
        if (lane + off < 32) suf += v;
    }
    __shared__ int wsum[32], wsuf[32];
    if (lane == 0) wsum[wid] = suf;
    __syncthreads();
    if (wid == 0) {
        int v = wsum[lane];
        int s = v;
        #pragma unroll
        for (int off = 1; off < 32; off <<= 1) {
            int t = __shfl_down_sync(0xffffffffu, s, off);
            if (lane + off < 32) s += t;
        }
        wsuf[lane] = s - v;
    }
    __syncthreads();
    int incl = suf + wsuf[wid];              // count(bins >= lo)
    int excl = incl - cs;                    // count(bins >= lo+64)
    if (excl < PRE && incl >= PRE) {
        int4 r[16];
        #pragma unroll
        for (int v = 0; v < 16; v++) r[v] = h4[v];
        int run = excl;
        int best = lo;
        bool found = false;
        #pragma unroll
        for (int v = 15; v >= 0; --v) {
            int4 x = r[v];
            run += x.w; if (run >= PRE && !found) { best = lo + 4 * v + 3; found = true; }
            run += x.z; if (run >= PRE && !found) { best = lo + 4 * v + 2; found = true; }
            run += x.y; if (run >= PRE && !found) { best = lo + 4 * v + 1; found = true; }
            run += x.x; if (run >= PRE && !found) { best = lo + 4 * v + 0; found = true; }
        }
        g_bstar[img] = (unsigned int)best;
    }
}

__global__ void k_compact(const float* __restrict__ scores, int A) {
    int img = blockIdx.y;
    int i = blockIdx.x * blockDim.x + threadIdx.x;
    int n2 = A >> 1;
    if (i >= n2) return;
    const float2* p = (const float2*)(scores + (size_t)img * A);
    unsigned int bst = g_bstar[img];
    float2 v = p[i];
    unsigned int k0 = flip_key(v.x), k1 = flip_key(v.y);
    if ((k0 >> 16) >= bst) {
        int pos = atomicAdd(&g_ccount[img], 1);
        if (pos < CAND_MAX)
            g_cand[img * CAND_MAX + pos] =
                ((unsigned long long)k0 << 32) |
                (unsigned long long)(0xFFFFFFFFu - (unsigned int)(2 * i));
    }
    if ((k1 >> 16) >= bst) {
        int pos = atomicAdd(&g_ccount[img], 1);
        if (pos < CAND_MAX)
            g_cand[img * CAND_MAX + pos] =
                ((unsigned long long)k1 << 32) |
                (unsigned long long)(0xFFFFFFFFu - (unsigned int)(2 * i + 1));
    }
}

// Partial rank: block = (chunk, jslice, img); exact u64 composite compares.
__global__ void k_rankpart() {
    int img = blockIdx.z;
    int slc = blockIdx.y;
    int blk = blockIdx.x;
    int tid = threadIdx.x;         // 256
    int n = g_ccount[img];
    if (n > CAND_MAX) n = CAND_MAX;
    if (blk * 256 >= n) return;
    int per = (n + JSPLIT - 1) / JSPLIT;
    int j0 = slc * per;
    int j1 = j0 + per; if (j1 > n) j1 = n;
    int m = j1 - j0;
    if (m <= 0) return;
    __shared__ unsigned long long s[SLICE_MAX + 8];
    const unsigned long long* cp = &g_cand[img * CAND_MAX];
    for (int t = tid; t < m; t += 256) s[t] = cp[j0 + t];
    __syncthreads();
    int i = blk * 256 + tid;
    if (i >= n) return;
    unsigned long long mine = cp[i];
    int rank = 0;
    const ulonglong2* s2 = (const ulonglong2*)s;
    int m2 = m >> 1;
    #pragma unroll 4
    for (int j = 0; j < m2; ++j) {
        ulonglong2 v = s2[j];
        rank += (v.x > mine);
        rank += (v.y > mine);
    }
    if (m & 1) rank += (s[m - 1] > mine);
    if (rank) atomicAdd(&g_rank[img * CAND_MAX + i], rank);
}

// decode + scatter by final rank
__global__ void k_scatter(const float* __restrict__ deltas,
                          const float* __restrict__ anchors, int A) {
    int img = blockIdx.y;
    int i = blockIdx.x * 256 + threadIdx.x;
    int n = g_ccount[img];
    if (n > CAND_MAX) n = CAND_MAX;
    if (i >= n) return;
    int rank = g_rank[img * CAND_MAX + i];
    if (rank >= PRE) return;
    unsigned long long mine = g_cand[img * CAND_MAX + i];
    unsigned int mk = (unsigned int)(mine >> 32);
    unsigned int ai  = 0xFFFFFFFFu - (unsigned int)(mine & 0xFFFFFFFFull);
    unsigned int u   = (mk & 0x80000000u) ? (mk ^ 0x80000000u) : ~mk;
    float logit = __uint_as_float(u);
    float a0 = anchors[ai * 4 + 0], a1 = anchors[ai * 4 + 1];
    float a2 = anchors[ai * 4 + 2], a3 = anchors[ai * 4 + 3];
    const float* dp = &deltas[((size_t)img * A + ai) * 4];
    float d0 = dp[0], d1 = dp[1];
    float d2 = fminf(dp[2], BBOX_CLIP), d3 = fminf(dp[3], BBOX_CLIP);
    float wa = a2 - a0, ha = a3 - a1;
    float cxa = a0 + 0.5f * wa, cya = a1 + 0.5f * ha;
    float cx = d0 * wa + cxa, cy = d1 * ha + cya;
    float w = expf(d2) * wa, h = expf(d3) * ha;
    float x1 = fminf(fmaxf(cx - 0.5f * w, 0.0f), IMGSZ);
    float y1 = fminf(fmaxf(cy - 0.5f * h, 0.0f), IMGSZ);
    float x2 = fminf(fmaxf(cx + 0.5f * w, 0.0f), IMGSZ);
    float y2 = fminf(fmaxf(cy + 0.5f * h, 0.0f), IMGSZ);
    float* bo = &g_boxes[(img * PREP + rank) * 4];
    bo[0] = x1; bo[1] = y1; bo[2] = x2; bo[3] = y2;
    g_logit[img * PREP + rank] = logit;
}

// suppression bitmask, upper triangle, packed launch, branch-free inner loop.
__global__ void k_mask() {
    int img = blockIdx.y;
    int t = blockIdx.x;
    int rb = 0, rem = t;
    #pragma unroll
    for (int r = 0; r < NCH; r++) {
        if (rem >= NCH - r) { rem -= NCH - r; rb++; } else break;
    }
    int cb = rb + rem;
    int tt = threadIdx.x;                       // 64
    __shared__ float4 cbox[64];
    __shared__ float carea[64];
    int j = cb * 64 + tt;
    const float* bx = &g_boxes[(img * PREP + j) * 4];   // zero rows beyond PRE
    float4 c4 = make_float4(bx[0], bx[1], bx[2], bx[3]);
    cbox[tt] = c4;
    carea[tt] = (c4.z - c4.x) * (c4.w - c4.y);
    __syncthreads();
    int i = rb * 64 + tt;
    const float* bi = &g_boxes[(img * PREP + i) * 4];
    float x1 = bi[0], y1 = bi[1], x2 = bi[2], y2 = bi[3];
    float ar = (x2 - x1) * (y2 - y1);
    unsigned int blo = 0, bhi = 0;
    #pragma unroll 8
    for (int k = 0; k < 32; k++) {
        float4 c = cbox[k];
        float aj = carea[k];
        float lx = fmaxf(x1, c.x), ly = fmaxf(y1, c.y);
        float rx = fminf(x2, c.z), ry = fminf(y2, c.w);
        float w = fmaxf(rx - lx, 0.f), hh = fmaxf(ry - ly, 0.f);
        float inter = w * hh;
        float iou = inter / (ar + aj - inter + 1e-9f);
        blo |= (iou > IOU_T ? 1u : 0u) << k;
    }
    #pragma unroll 8
    for (int k = 0; k < 32; k++) {
        float4 c = cbox[k + 32];
        float aj = carea[k + 32];
        float lx = fmaxf(x1, c.x), ly = fmaxf(y1, c.y);
        float rx = fminf(x2, c.z), ry = fminf(y2, c.w);
        float w = fmaxf(rx - lx, 0.f), hh = fmaxf(ry - ly, 0.f);
        float inter = w * hh;
        float iou = inter / (ar + aj - inter + 1e-9f);
        bhi |= (iou > IOU_T ? 1u : 0u) << k;
    }
    unsigned long long bits = ((unsigned long long)bhi << 32) | blo;
    if (cb == rb) bits &= (~1ULL) << tt;        // keep only k > i on diagonal
    g_mask[((size_t)img * PREP + i) * NCH + cb] = bits;
}

// greedy NMS via Jacobi fixed-point iteration (fully parallel, exact).
//   keep^0 = alive; keep^{t+1}[i] = alive[i] & ~OR_{j<i, keep^t[j]} sup[j][i]
//   Unique fixed point == greedy NMS result; stop when nothing changes.
//   Thread layout: col = tid&31 (mask word), grp = tid>>5 (4 row-chunks each).
//   Only chunks rc <= col are read (M's upper triangle is the written part).
__global__ void __launch_bounds__(256, 1) k_scanout(float* __restrict__ out) {
    int img = blockIdx.x;
    int tid = threadIdx.x;     // 256
    int col = tid & 31, grp = tid >> 5;    // 8 groups x 32 cols
    __shared__ unsigned long long keep[NCH];
    __shared__ unsigned long long partial[8][NCH];
    __shared__ int pref[NCH];
    __shared__ int s_changed;
    const unsigned long long* M = &g_mask[(size_t)img * PREP * NCH];

    if (tid < NCH) {
        unsigned long long lim = (tid == NCH - 1)
            ? ((1ULL << (PRE - 64 * (NCH - 1))) - 1ULL) : ~0ULL;
        keep[tid] = lim;
    }
    if (tid == 0) s_changed = 1;
    __syncthreads();

    for (int iter = 0; iter < 2048; ++iter) {
        if (!s_changed) break;         // uniform read (post-sync)
        __syncthreads();               // everyone has read the flag
        if (tid == 0) s_changed = 0;
        // partial dead for (grp, col): OR of M[r][col] over kept rows r in
        // this grp's 4 row-chunks, restricted to valid triangle rc <= col.
        unsigned long long acc = 0ULL;
        #pragma unroll
        for (int q = 0; q < 4; q++) {
            int rc = grp * 4 + q;
            if (rc > col) break;
            unsigned long long w = keep[rc];
            const unsigned long long* Mr = M + (size_t)rc * 64 * NCH + col;
            while (w) {
                int b = __ffsll((long long)w) - 1;
                w &= w - 1ULL;
                acc |= Mr[(size_t)b * NCH];
            }
        }
        partial[grp][col] = acc;
        __syncthreads();
        if (tid < NCH) {
            unsigned long long dead = 0ULL;
            #pragma unroll
            for (int g = 0; g < 8; g++) dead |= partial[g][tid];
            unsigned long long lim = (tid == NCH - 1)
                ? ((1ULL << (PRE - 64 * (NCH - 1))) - 1ULL) : ~0ULL;
            unsigned long long nk = lim & ~dead;
            if (nk != keep[tid]) { keep[tid] = nk; s_changed = 1; }
        }
        __syncthreads();               // keep + flag visible for next iter
    }

    if (tid == 0) {
        int r = 0;
        for (int c = 0; c < NCH; c++) { pref[c] = r; r += __popcll(keep[c]); }
    }
    __syncthreads();
    for (int t = tid; t < POST * 5; t += 256) out[(size_t)img * POST * 5 + t] = 0.0f;
    __syncthreads();
    for (int i = tid; i < PRE; i += 256) {
        int c = i >> 6, b = i & 63;
        unsigned long long wd = keep[c];
        if ((wd >> b) & 1ULL) {
            int rank = pref[c] + __popcll(wd & ((1ULL << b) - 1ULL));
            if (rank < POST) {
                const float* bo = &g_boxes[(img * PREP + i) * 4];
                float lg = g_logit[img * PREP + i];
                float p = 1.0f / (1.0f + expf(-lg));
                float* o = &out[((size_t)img * POST + rank) * 5];
                o[0] = bo[0]; o[1] = bo[1]; o[2] = bo[2]; o[3] = bo[3]; o[4] = p;
            }
        }
    }
}

// ---------------- launch ----------------
extern "C" void kernel_launch(void* const* d_in, const int* in_sizes, int n_in,
                              void* d_out, int out_size) {
    const float* scores  = (const float*)d_in[0];
    const float* deltas  = (const float*)d_in[1];
    const float* anchors = (const float*)d_in[2];
    float* out = (float*)d_out;

    int A = in_sizes[2] / 4;
    int B = in_sizes[0] / A;
    if (B > BMAX) B = BMAX;

    void* hist_ptr = nullptr;  cudaGetSymbolAddress(&hist_ptr, g_hist);
    void* cnt_ptr  = nullptr;  cudaGetSymbolAddress(&cnt_ptr,  g_ccount);
    void* rank_ptr = nullptr;  cudaGetSymbolAddress(&rank_ptr, g_rank);
    cudaMemsetAsync(hist_ptr, 0, (size_t)B * NBINS * sizeof(int));
    cudaMemsetAsync(cnt_ptr,  0, (size_t)BMAX * sizeof(int));
    cudaMemsetAsync(rank_ptr, 0, (size_t)B * CAND_MAX * sizeof(int));

    int n2 = A >> 1;
    dim3 gh((n2 + 255) / 256, B);
    k_hist<<<gh, 256>>>(scores, A);
    k_select<<<B, 1024>>>();
    k_compact<<<gh, 256>>>(scores, A);
    k_rankpart<<<dim3(CAND_MAX / 256, JSPLIT, B), 256>>>();
    k_scatter<<<dim3(CAND_MAX / 256, B), 256>>>(deltas, anchors, A);
    k_mask<<<dim3(TRI_BLOCKS, B), 64>>>();
    k_scanout<<<B, 256>>>(out);
}

// round 17
// speedup vs baseline: 1.7516x; 1.7516x over previous
#include <cuda_runtime.h>
#include <cstdint>

// Problem constants
#define BMAX 16
#define PRE 2000
#define PREP 2048          // padded
#define NCH 32             // PREP/64
#define POST 1000
#define CAND_MAX 4096
#define NBINS 65536
#define IOU_T 0.7f
#define IMGSZ 800.0f
#define BBOX_CLIP 4.135166556742356f   // log(1000/16)
#define TRI_BLOCKS ((NCH * (NCH + 1)) / 2)   // 528 upper-triangle chunk pairs
#define JSPLIT 4
#define SLICE_MAX (CAND_MAX / JSPLIT)        // 1024

// ---------------- device scratch (no allocation allowed) ----------------
__device__ int                g_hist[BMAX * NBINS];      // 4 MB
__device__ unsigned int       g_bstar[BMAX];
__device__ int                g_ccount[BMAX];
__device__ unsigned long long g_cand[BMAX * CAND_MAX];   // 0.5 MB
__device__ int                g_rank[BMAX * CAND_MAX];   // 0.25 MB
__device__ float              g_boxes[BMAX * PREP * 4];  // 0.5 MB (rows >= PRE stay zero)
__device__ float              g_logit[BMAX * PREP];
__device__ unsigned long long g_mask[BMAX * PREP * NCH]; // 8 MB (upper triangle valid)
__device__ unsigned int       g_colnz32[BMAX * NCH * NCH * 2]; // nonzero-word bitmap

__device__ __forceinline__ unsigned int flip_key(float f) {
    unsigned int u = __float_as_uint(f);
    return (u & 0x80000000u) ? ~u : (u | 0x80000000u);
}

// ---------------- kernels ----------------
// float2 vectorized: 2 elems per LDG.64
__global__ void k_hist(const float* __restrict__ scores, int A) {
    int img = blockIdx.y;
    int i = blockIdx.x * blockDim.x + threadIdx.x;
    int n2 = A >> 1;
    if (i >= n2) return;
    const float2* p = (const float2*)(scores + (size_t)img * A);
    float2 v = p[i];
    atomicAdd(&g_hist[img * NBINS + (flip_key(v.x) >> 16)], 1);
    atomicAdd(&g_hist[img * NBINS + (flip_key(v.y) >> 16)], 1);
}

// one block (1024 thr) per image: boundary bin b*
__global__ void k_select() {
    int img = blockIdx.x;
    int tid = threadIdx.x;           // 1024
    int lane = tid & 31, wid = tid >> 5;
    const int* h = &g_hist[img * NBINS];
    int lo = tid * 64;
    int cs = 0;
    const int4* h4 = (const int4*)(h + lo);
    #pragma unroll
    for (int v = 0; v < 16; v++) { int4 x = h4[v]; cs += x.x + x.y + x.z + x.w; }
    int suf = cs;
    #pragma unroll
    for (int off = 1; off < 32; off <<= 1) {
        int v = __shfl_down_sync(0xffffffffu, suf, off);
        if (lane + off < 32) suf += v;
    }
    __shared__ int wsum[32], wsuf[32];
    if (lane == 0) wsum[wid] = suf;
    __syncthreads();
    if (wid == 0) {
        int v = wsum[lane];
        int s = v;
        #pragma unroll
        for (int off = 1; off < 32; off <<= 1) {
            int t = __shfl_down_sync(0xffffffffu, s, off);
            if (lane + off < 32) s += t;
        }
        wsuf[lane] = s - v;
    }
    __syncthreads();
    int incl = suf + wsuf[wid];              // count(bins >= lo)
    int excl = incl - cs;                    // count(bins >= lo+64)
    if (excl < PRE && incl >= PRE) {
        int4 r[16];
        #pragma unroll
        for (int v = 0; v < 16; v++) r[v] = h4[v];
        int run = excl;
        int best = lo;
        bool found = false;
        #pragma unroll
        for (int v = 15; v >= 0; --v) {
            int4 x = r[v];
            run += x.w; if (run >= PRE && !found) { best = lo + 4 * v + 3; found = true; }
            run += x.z; if (run >= PRE && !found) { best = lo + 4 * v + 2; found = true; }
            run += x.y; if (run >= PRE && !found) { best = lo + 4 * v + 1; found = true; }
            run += x.x; if (run >= PRE && !found) { best = lo + 4 * v + 0; found = true; }
        }
        g_bstar[img] = (unsigned int)best;
    }
}

__global__ void k_compact(const float* __restrict__ scores, int A) {
    int img = blockIdx.y;
    int i = blockIdx.x * blockDim.x + threadIdx.x;
    int n2 = A >> 1;
    if (i >= n2) return;
    const float2* p = (const float2*)(scores + (size_t)img * A);
    unsigned int bst = g_bstar[img];
    float2 v = p[i];
    unsigned int k0 = flip_key(v.x), k1 = flip_key(v.y);
    if ((k0 >> 16) >= bst) {
        int pos = atomicAdd(&g_ccount[img], 1);
        if (pos < CAND_MAX)
            g_cand[img * CAND_MAX + pos] =
                ((unsigned long long)k0 << 32) |
                (unsigned long long)(0xFFFFFFFFu - (unsigned int)(2 * i));
    }
    if ((k1 >> 16) >= bst) {
        int pos = atomicAdd(&g_ccount[img], 1);
        if (pos < CAND_MAX)
            g_cand[img * CAND_MAX + pos] =
                ((unsigned long long)k1 << 32) |
                (unsigned long long)(0xFFFFFFFFu - (unsigned int)(2 * i + 1));
    }
}

// Partial rank: block = (chunk, jslice, img); exact u64 composite compares.
__global__ void k_rankpart() {
    int img = blockIdx.z;
    int slc = blockIdx.y;
    int blk = blockIdx.x;
    int tid = threadIdx.x;         // 256
    int n = g_ccount[img];
    if (n > CAND_MAX) n = CAND_MAX;
    if (blk * 256 >= n) return;
    int per = (n + JSPLIT - 1) / JSPLIT;
    int j0 = slc * per;
    int j1 = j0 + per; if (j1 > n) j1 = n;
    int m = j1 - j0;
    if (m <= 0) return;
    __shared__ unsigned long long s[SLICE_MAX + 8];
    const unsigned long long* cp = &g_cand[img * CAND_MAX];
    for (int t = tid; t < m; t += 256) s[t] = cp[j0 + t];
    __syncthreads();
    int i = blk * 256 + tid;
    if (i >= n) return;
    unsigned long long mine = cp[i];
    int rank = 0;
    const ulonglong2* s2 = (const ulonglong2*)s;
    int m2 = m >> 1;
    #pragma unroll 4
    for (int j = 0; j < m2; ++j) {
        ulonglong2 v = s2[j];
        rank += (v.x > mine);
        rank += (v.y > mine);
    }
    if (m & 1) rank += (s[m - 1] > mine);
    if (rank) atomicAdd(&g_rank[img * CAND_MAX + i], rank);
}

// decode + scatter by final rank
__global__ void k_scatter(const float* __restrict__ deltas,
                          const float* __restrict__ anchors, int A) {
    int img = blockIdx.y;
    int i = blockIdx.x * 256 + threadIdx.x;
    int n = g_ccount[img];
    if (n > CAND_MAX) n = CAND_MAX;
    if (i >= n) return;
    int rank = g_rank[img * CAND_MAX + i];
    if (rank >= PRE) return;
    unsigned long long mine = g_cand[img * CAND_MAX + i];
    unsigned int mk = (unsigned int)(mine >> 32);
    unsigned int ai  = 0xFFFFFFFFu - (unsigned int)(mine & 0xFFFFFFFFull);
    unsigned int u   = (mk & 0x80000000u) ? (mk ^ 0x80000000u) : ~mk;
    float logit = __uint_as_float(u);
    float a0 = anchors[ai * 4 + 0], a1 = anchors[ai * 4 + 1];
    float a2 = anchors[ai * 4 + 2], a3 = anchors[ai * 4 + 3];
    const float* dp = &deltas[((size_t)img * A + ai) * 4];
    float d0 = dp[0], d1 = dp[1];
    float d2 = fminf(dp[2], BBOX_CLIP), d3 = fminf(dp[3], BBOX_CLIP);
    float wa = a2 - a0, ha = a3 - a1;
    float cxa = a0 + 0.5f * wa, cya = a1 + 0.5f * ha;
    float cx = d0 * wa + cxa, cy = d1 * ha + cya;
    float w = expf(d2) * wa, h = expf(d3) * ha;
    float x1 = fminf(fmaxf(cx - 0.5f * w, 0.0f), IMGSZ);
    float y1 = fminf(fmaxf(cy - 0.5f * h, 0.0f), IMGSZ);
    float x2 = fminf(fmaxf(cx + 0.5f * w, 0.0f), IMGSZ);
    float y2 = fminf(fmaxf(cy + 0.5f * h, 0.0f), IMGSZ);
    float* bo = &g_boxes[(img * PREP + rank) * 4];
    bo[0] = x1; bo[1] = y1; bo[2] = x2; bo[3] = y2;
    g_logit[img * PREP + rank] = logit;
}

// suppression bitmask, upper triangle, packed launch, branch-free inner loop.
// Also records, per (rowchunk, colchunk), which rows have a NONZERO word
// (one ballot per warp) -> g_colnz32. Scan uses this to touch only nonzero
// words (~700 suppression pairs of 4M bits).
__global__ void k_mask() {
    int img = blockIdx.y;
    int t = blockIdx.x;
    int rb = 0, rem = t;
    #pragma unroll
    for (int r = 0; r < NCH; r++) {
        if (rem >= NCH - r) { rem -= NCH - r; rb++; } else break;
    }
    int cb = rb + rem;
    int tt = threadIdx.x;                       // 64
    __shared__ float4 cbox[64];
    __shared__ float carea[64];
    int j = cb * 64 + tt;
    const float* bx = &g_boxes[(img * PREP + j) * 4];   // zero rows beyond PRE
    float4 c4 = make_float4(bx[0], bx[1], bx[2], bx[3]);
    cbox[tt] = c4;
    carea[tt] = (c4.z - c4.x) * (c4.w - c4.y);
    __syncthreads();
    int i = rb * 64 + tt;
    const float* bi = &g_boxes[(img * PREP + i) * 4];
    float x1 = bi[0], y1 = bi[1], x2 = bi[2], y2 = bi[3];
    float ar = (x2 - x1) * (y2 - y1);
    unsigned int blo = 0, bhi = 0;
    #pragma unroll 8
    for (int k = 0; k < 32; k++) {
        float4 c = cbox[k];
        float aj = carea[k];
        float lx = fmaxf(x1, c.x), ly = fmaxf(y1, c.y);
        float rx = fminf(x2, c.z), ry = fminf(y2, c.w);
        float w = fmaxf(rx - lx, 0.f), hh = fmaxf(ry - ly, 0.f);
        float inter = w * hh;
        float iou = inter / (ar + aj - inter + 1e-9f);
        blo |= (iou > IOU_T ? 1u : 0u) << k;
    }
    #pragma unroll 8
    for (int k = 0; k < 32; k++) {
        float4 c = cbox[k + 32];
        float aj = carea[k + 32];
        float lx = fmaxf(x1, c.x), ly = fmaxf(y1, c.y);
        float rx = fminf(x2, c.z), ry = fminf(y2, c.w);
        float w = fmaxf(rx - lx, 0.f), hh = fmaxf(ry - ly, 0.f);
        float inter = w * hh;
        float iou = inter / (ar + aj - inter + 1e-9f);
        bhi |= (iou > IOU_T ? 1u : 0u) << k;
    }
    unsigned long long bits = ((unsigned long long)bhi << 32) | blo;
    if (cb == rb) bits &= (~1ULL) << tt;        // keep only k > i on diagonal
    g_mask[((size_t)img * PREP + i) * NCH + cb] = bits;
    unsigned int nz = __ballot_sync(0xffffffffu, bits != 0ULL);
    if ((tt & 31) == 0)
        g_colnz32[(((size_t)img * NCH + rb) * NCH + cb) * 2 + (tt >> 5)] = nz;
}

// greedy scan v4 (sparse Gauss-Seidel):
//  chain: thread 0, only bits with nonzero diag word (W = colnz[c][c]).
//  apply: one thread per column word (no atomics, single writer), loading
//  only nonzero mask words (colnz & keep).
__global__ void __launch_bounds__(256, 1) k_scanout(float* __restrict__ out) {
    int img = blockIdx.x;
    int tid = threadIdx.x;     // 256
    __shared__ unsigned long long diagcol[NCH * 64];   // 16 KB
    __shared__ unsigned long long scolnz[NCH * NCH];   // 8 KB
    __shared__ unsigned long long removed[NCH];
    __shared__ unsigned long long keep[NCH];
    __shared__ int pref[NCH];
    const unsigned long long* M = &g_mask[(size_t)img * PREP * NCH];
    const unsigned int* CZ = &g_colnz32[(size_t)img * NCH * NCH * 2];

    for (int t = tid; t < NCH * 64; t += 256) {
        int c = t >> 6, r = t & 63;
        diagcol[t] = M[(size_t)(c * 64 + r) * NCH + c];
    }
    for (int t = tid; t < NCH * NCH; t += 256) {
        int rb = t >> 5, cb = t & 31;
        if (cb >= rb) {
            unsigned int lo = CZ[(rb * NCH + cb) * 2 + 0];
            unsigned int hi = CZ[(rb * NCH + cb) * 2 + 1];
            scolnz[t] = ((unsigned long long)hi << 32) | lo;
        } else {
            scolnz[t] = 0ULL;
        }
    }
    if (tid < NCH) removed[tid] = 0ULL;
    __syncthreads();

    for (int c = 0; c < NCH; ++c) {
        if (tid == 0) {
            unsigned long long lim = (c == NCH - 1)
                ? ((1ULL << (PRE - 64 * (NCH - 1))) - 1ULL) : ~0ULL;
            unsigned long long dead = removed[c] | ~lim;
            unsigned long long W = scolnz[c * NCH + c];  // rows w/ nonzero diag word
            while (W) {
                int b = __ffsll((long long)W) - 1;
                W &= W - 1ULL;
                if (!((dead >> b) & 1ULL))
                    dead |= diagcol[c * 64 + b];         // only sets bits > b
            }
            keep[c] = lim & ~dead;
        }
        __syncthreads();
        if (tid < NCH && tid > c) {
            int col = tid;
            unsigned long long w = scolnz[c * NCH + col] & keep[c];
            if (w) {
                unsigned long long acc = 0ULL;
                while (w) {
                    int b = __ffsll((long long)w) - 1;
                    w &= w - 1ULL;
                    acc |= M[(size_t)(c * 64 + b) * NCH + col];
                }
                removed[col] |= acc;   // single writer per col
            }
        }
        __syncthreads();
    }

    if (tid == 0) {
        int r = 0;
        for (int c = 0; c < NCH; c++) { pref[c] = r; r += __popcll(keep[c]); }
    }
    __syncthreads();
    for (int t = tid; t < POST * 5; t += 256) out[(size_t)img * POST * 5 + t] = 0.0f;
    __syncthreads();
    for (int i = tid; i < PRE; i += 256) {
        int c = i >> 6, b = i & 63;
        unsigned long long wd = keep[c];
        if ((wd >> b) & 1ULL) {
            int rank = pref[c] + __popcll(wd & ((1ULL << b) - 1ULL));
            if (rank < POST) {
                const float* bo = &g_boxes[(img * PREP + i) * 4];
                float lg = g_logit[img * PREP + i];
                float p = 1.0f / (1.0f + expf(-lg));
                float* o = &out[((size_t)img * POST + rank) * 5];
                o[0] = bo[0]; o[1] = bo[1]; o[2] = bo[2]; o[3] = bo[3]; o[4] = p;
            }
        }
    }
}

// ---------------- launch ----------------
extern "C" void kernel_launch(void* const* d_in, const int* in_sizes, int n_in,
                              void* d_out, int out_size) {
    const float* scores  = (const float*)d_in[0];
    const float* deltas  = (const float*)d_in[1];
    const float* anchors = (const float*)d_in[2];
    float* out = (float*)d_out;

    int A = in_sizes[2] / 4;
    int B = in_sizes[0] / A;
    if (B > BMAX) B = BMAX;

    void* hist_ptr = nullptr;  cudaGetSymbolAddress(&hist_ptr, g_hist);
    void* cnt_ptr  = nullptr;  cudaGetSymbolAddress(&cnt_ptr,  g_ccount);
    void* rank_ptr = nullptr;  cudaGetSymbolAddress(&rank_ptr, g_rank);
    cudaMemsetAsync(hist_ptr, 0, (size_t)B * NBINS * sizeof(int));
    cudaMemsetAsync(cnt_ptr,  0, (size_t)BMAX * sizeof(int));
    cudaMemsetAsync(rank_ptr, 0, (size_t)B * CAND_MAX * sizeof(int));

    int n2 = A >> 1;
    dim3 gh((n2 + 255) / 256, B);
    k_hist<<<gh, 256>>>(scores, A);
    k_select<<<B, 1024>>>();
    k_compact<<<gh, 256>>>(scores, A);
    k_rankpart<<<dim3(CAND_MAX / 256, JSPLIT, B), 256>>>();
    k_scatter<<<dim3(CAND_MAX / 256, B), 256>>>(deltas, anchors, A);
    k_mask<<<dim3(TRI_BLOCKS, B), 64>>>();
    k_scanout<<<B, 256>>>(out);
}